// round 9
// baseline (speedup 1.0000x reference)
#include <cuda_runtime.h>
#include <cstdint>

#define DINLINE __device__ __forceinline__

constexpr int NPTS   = 100000;
constexpr int NPAIRS = 50000;
constexpr int KOFF   = 27;
constexpr int C      = 128;
constexpr int TILE_M = 128;
constexpr int GX     = 10;                                // 270 CTAs = 1 wave @ 2/SM
constexpr int NTILES = (NPAIRS + TILE_M - 1) / TILE_M;    // 391
constexpr int THREADS = 128;                              // 4 warps, 32 output cols each
constexpr int ASTR   = 132;                               // padded row stride (floats)

// scratch: intermediate activations + pre-transposed tf32 weights
__device__ float g_h[(size_t)NPTS * C];
__device__ float g_Wt[(size_t)2 * KOFF * C * C];          // [conv][k][n][c], tf32-rounded

// ---------------------------------------------------------------- helpers
DINLINE uint32_t cvt_tf32(float f) {
    uint32_t r; asm("cvt.rna.tf32.f32 %0, %1;" : "=r"(r) : "f"(f)); return r;
}
DINLINE void red_add_v2(float* a, float x, float y) {
    asm volatile("red.global.add.v2.f32 [%0], {%1,%2};"
                 :: "l"(a), "f"(x), "f"(y) : "memory");
}
// m16n8k8 tf32 mma: A row-major frag {a0..a3}, B col-major frag {b0,b1}, fp32 acc
DINLINE void mma_tf32(float c[4], uint32_t a0, uint32_t a1, uint32_t a2, uint32_t a3,
                      uint32_t b0, uint32_t b1) {
    asm volatile(
        "mma.sync.aligned.m16n8k8.row.col.f32.tf32.tf32.f32 "
        "{%0,%1,%2,%3}, {%4,%5,%6,%7}, {%8,%9}, {%0,%1,%2,%3};"
        : "+f"(c[0]), "+f"(c[1]), "+f"(c[2]), "+f"(c[3])
        : "r"(a0), "r"(a1), "r"(a2), "r"(a3), "r"(b0), "r"(b1));
}

// Gather 128 rows into smem, tf32-rounded, with a 4x4 transpose permutation inside
// each 16-col group: permuted pos 16kp + 4*(o%4) + (o>>2) for original col o in [0,16).
// Result: one LDS.128 at (row, 16kp + 4*tig) yields {a0,a2} for k-steps 2kp and 2kp+1.
// 128 threads: one thread per row, 32 float4 loads each.
DINLINE void gather_tile(float* As, const float* __restrict__ X,
                         const int* __restrict__ im, int p0, int do_relu, int tid) {
    int r = tid;
    int p  = p0 + r;
    int pv = p < NPAIRS ? p : NPAIRS - 1;        // clamp; invalid rows never scattered
    int src = im[pv];
    const float4* xr = reinterpret_cast<const float4*>(X + (size_t)src * C);
    float* arow = As + r * ASTR;
    #pragma unroll
    for (int kp = 0; kp < 8; kp++) {
        float4 x0 = xr[kp * 4 + 0], x1 = xr[kp * 4 + 1];
        float4 x2 = xr[kp * 4 + 2], x3 = xr[kp * 4 + 3];
        if (do_relu) {
            x0.x=fmaxf(x0.x,0.f); x0.y=fmaxf(x0.y,0.f); x0.z=fmaxf(x0.z,0.f); x0.w=fmaxf(x0.w,0.f);
            x1.x=fmaxf(x1.x,0.f); x1.y=fmaxf(x1.y,0.f); x1.z=fmaxf(x1.z,0.f); x1.w=fmaxf(x1.w,0.f);
            x2.x=fmaxf(x2.x,0.f); x2.y=fmaxf(x2.y,0.f); x2.z=fmaxf(x2.z,0.f); x2.w=fmaxf(x2.w,0.f);
            x3.x=fmaxf(x3.x,0.f); x3.y=fmaxf(x3.y,0.f); x3.z=fmaxf(x3.z,0.f); x3.w=fmaxf(x3.w,0.f);
        }
        uint4 o0 = { cvt_tf32(x0.x), cvt_tf32(x1.x), cvt_tf32(x2.x), cvt_tf32(x3.x) };
        uint4 o1 = { cvt_tf32(x0.y), cvt_tf32(x1.y), cvt_tf32(x2.y), cvt_tf32(x3.y) };
        uint4 o2 = { cvt_tf32(x0.z), cvt_tf32(x1.z), cvt_tf32(x2.z), cvt_tf32(x3.z) };
        uint4 o3 = { cvt_tf32(x0.w), cvt_tf32(x1.w), cvt_tf32(x2.w), cvt_tf32(x3.w) };
        *reinterpret_cast<uint4*>(arow + kp * 16 +  0) = o0;
        *reinterpret_cast<uint4*>(arow + kp * 16 +  4) = o1;
        *reinterpret_cast<uint4*>(arow + kp * 16 +  8) = o2;
        *reinterpret_cast<uint4*>(arow + kp * 16 + 12) = o3;
    }
}

// ---------------------------------------------------------------- main kernel
// One CTA = one kernel offset k; persistent over P-tiles t = bx, bx+GX, ...
// 4 warps: warp w owns output cols [32w, 32w+32); its B fragments (W[k]^T slice,
// 128 regs) stay in registers for the whole kernel. A comes from smem per tile.
// 2 CTAs/SM: one gathers while the other runs MMAs.
__global__ void __launch_bounds__(THREADS, 2)
spconv_mma_kernel(const float* __restrict__ X,
                  const float* __restrict__ Wt,     // [KOFF][n][c], tf32-rounded
                  const int* __restrict__ in_map,
                  const int* __restrict__ out_map,
                  float* __restrict__ Y,
                  int do_relu)
{
    extern __shared__ float As[];                  // [128][ASTR]
    const int tid = threadIdx.x;
    const int wid = tid >> 5, lid = tid & 31;
    const int g = lid >> 2, tig = lid & 3;         // groupID / thread-in-group
    const int k = blockIdx.y;
    const int* im = in_map  + k * NPAIRS;
    const int* om = out_map + k * NPAIRS;
    const int n0 = wid * 32;

    // ---- load B fragments once: bfr[ks][nb][i] = Wt[k][n0+8nb+g][8ks+tig+4i] ----
    uint32_t bfr[16][4][2];
    {
        const float* wk = Wt + (size_t)k * C * C;
        #pragma unroll
        for (int ks = 0; ks < 16; ks++)
            #pragma unroll
            for (int nb = 0; nb < 4; nb++) {
                const float* wrow = wk + (n0 + 8 * nb + g) * C + 8 * ks + tig;
                bfr[ks][nb][0] = __float_as_uint(wrow[0]);
                bfr[ks][nb][1] = __float_as_uint(wrow[4]);
            }
    }

    for (int t = blockIdx.x; t < NTILES; t += GX) {
        __syncthreads();                           // prev tile's reads done
        gather_tile(As, X, im, t * TILE_M, do_relu, tid);
        __syncthreads();

        #pragma unroll 1
        for (int mb = 0; mb < 8; mb++) {
            float acc[4][4] = {{0.f,0.f,0.f,0.f},{0.f,0.f,0.f,0.f},
                               {0.f,0.f,0.f,0.f},{0.f,0.f,0.f,0.f}};
            const float* a_lo = As + (mb * 16 + g    ) * ASTR;
            const float* a_hi = As + (mb * 16 + g + 8) * ASTR;
            #pragma unroll
            for (int kp = 0; kp < 8; kp++) {
                uint4 lo = *reinterpret_cast<const uint4*>(a_lo + kp * 16 + 4 * tig);
                uint4 hi = *reinterpret_cast<const uint4*>(a_hi + kp * 16 + 4 * tig);
                #pragma unroll
                for (int nb = 0; nb < 4; nb++) {
                    // k-step 2kp:   A frags (lo.x,hi.x,lo.y,hi.y)
                    mma_tf32(acc[nb], lo.x, hi.x, lo.y, hi.y,
                             bfr[2*kp  ][nb][0], bfr[2*kp  ][nb][1]);
                    // k-step 2kp+1: A frags (lo.z,hi.z,lo.w,hi.w)
                    mma_tf32(acc[nb], lo.z, hi.z, lo.w, hi.w,
                             bfr[2*kp+1][nb][0], bfr[2*kp+1][nb][1]);
                }
            }
            // scatter: c0,c1 -> row g; c2,c3 -> row g+8; cols n0+8nb+2tig+{0,1}
            int p_lo = t * TILE_M + mb * 16 + g;
            int p_hi = p_lo + 8;
            if (p_lo < NPAIRS) {
                float* y = Y + (size_t)om[p_lo] * C + n0 + 2 * tig;
                #pragma unroll
                for (int nb = 0; nb < 4; nb++)
                    red_add_v2(y + 8 * nb, acc[nb][0], acc[nb][1]);
            }
            if (p_hi < NPAIRS) {
                float* y = Y + (size_t)om[p_hi] * C + n0 + 2 * tig;
                #pragma unroll
                for (int nb = 0; nb < 4; nb++)
                    red_add_v2(y + 8 * nb, acc[nb][2], acc[nb][3]);
            }
        }
    }
}

// ---------------------------------------------------------------- small kernels
__global__ void wt_kernel(const float* __restrict__ W0, const float* __restrict__ W1) {
    int i = blockIdx.x * blockDim.x + threadIdx.x;       // over KOFF*C*C, layout [k][n][c]
    if (i >= KOFF * C * C) return;
    int k = i / (C * C);
    int rem = i % (C * C);
    int n = rem / C, c = rem % C;
    g_Wt[i] = __uint_as_float(cvt_tf32(W0[(size_t)k * C * C + c * C + n]));
    g_Wt[(size_t)KOFF * C * C + i] =
        __uint_as_float(cvt_tf32(W1[(size_t)k * C * C + c * C + n]));
}

__global__ void init_h_kernel(const float* __restrict__ b0) {
    int i = blockIdx.x * blockDim.x + threadIdx.x;       // float4 index
    if (i < NPTS * C / 4)
        reinterpret_cast<float4*>(g_h)[i] =
            reinterpret_cast<const float4*>(b0)[i & (C / 4 - 1)];
}

__global__ void init_out_kernel(const float* __restrict__ feat,
                                const float* __restrict__ b1,
                                float* __restrict__ out) {
    int i = blockIdx.x * blockDim.x + threadIdx.x;
    if (i < NPTS * C / 4) {
        float4 f = reinterpret_cast<const float4*>(feat)[i];
        float4 b = reinterpret_cast<const float4*>(b1)[i & (C / 4 - 1)];
        f.x += b.x; f.y += b.y; f.z += b.z; f.w += b.w;
        reinterpret_cast<float4*>(out)[i] = f;
    }
}

// ---------------------------------------------------------------- launch
extern "C" void kernel_launch(void* const* d_in, const int* in_sizes, int n_in,
                              void* d_out, int out_size) {
    const float* feat    = (const float*)d_in[0];
    const int*   in_map  = (const int*)  d_in[1];
    const int*   out_map = (const int*)  d_in[2];
    const float* W0      = (const float*)d_in[3];
    const float* b0      = (const float*)d_in[4];
    const float* W1      = (const float*)d_in[5];
    const float* b1      = (const float*)d_in[6];
    float*       out     = (float*)d_out;

    float* h  = nullptr; cudaGetSymbolAddress((void**)&h,  g_h);
    float* wt = nullptr; cudaGetSymbolAddress((void**)&wt, g_Wt);

    const int smem_bytes = TILE_M * ASTR * (int)sizeof(float);   // 67584
    cudaFuncSetAttribute(spconv_mma_kernel,
                         cudaFuncAttributeMaxDynamicSharedMemorySize, smem_bytes);

    const int nv4 = NPTS * C / 4;
    dim3 ggrid(GX, KOFF);

    wt_kernel<<<(KOFF * C * C + 255) / 256, 256>>>(W0, W1);

    // conv0: h = b0; h += scatter(gather(x) @ W0)   (relu deferred into conv1's gather)
    init_h_kernel<<<(nv4 + 255) / 256, 256>>>(b0);
    spconv_mma_kernel<<<ggrid, THREADS, smem_bytes>>>(feat, wt, in_map, out_map, h, 0);

    // conv1: out = x + b1; out += scatter(gather(relu(h)) @ W1)
    init_out_kernel<<<(nv4 + 255) / 256, 256>>>(feat, b1, out);
    spconv_mma_kernel<<<ggrid, THREADS, smem_bytes>>>(h, wt + (size_t)KOFF * C * C,
                                                     in_map, out_map, out, 1);
}

// round 10
// speedup vs baseline: 1.4211x; 1.4211x over previous
#include <cuda_runtime.h>
#include <cstdint>

#define DINLINE __device__ __forceinline__

constexpr int NPTS   = 100000;
constexpr int NPAIRS = 50000;
constexpr int KOFF   = 27;
constexpr int C      = 128;
constexpr int TILE_M = 128;
constexpr int GX     = 5;                                 // 135 CTAs @ 1/SM = 1 wave
constexpr int NTILES = (NPAIRS + TILE_M - 1) / TILE_M;    // 391
constexpr int THREADS = 256;
constexpr int BUFW   = TILE_M * C;                        // 16384 words / buffer

// scratch: intermediate activations + pre-transposed tf32 weights
__device__ float g_h[(size_t)NPTS * C];
__device__ float g_Wt[(size_t)2 * KOFF * C * C];          // [conv][k][n][c], tf32-rounded

// ---------------------------------------------------------------- helpers
DINLINE uint32_t cvt_tf32(float f) {
    uint32_t r; asm("cvt.rna.tf32.f32 %0, %1;" : "=r"(r) : "f"(f)); return r;
}
DINLINE void red_add_v2(float* a, float x, float y) {
    asm volatile("red.global.add.v2.f32 [%0], {%1,%2};"
                 :: "l"(a), "f"(x), "f"(y) : "memory");
}
// m16n8k8 tf32 mma: A row-major frag {a0..a3}, B col-major frag {b0,b1}, fp32 acc
DINLINE void mma_tf32(float c[4], uint32_t a0, uint32_t a1, uint32_t a2, uint32_t a3,
                      uint32_t b0, uint32_t b1) {
    asm volatile(
        "mma.sync.aligned.m16n8k8.row.col.f32.tf32.tf32.f32 "
        "{%0,%1,%2,%3}, {%4,%5,%6,%7}, {%8,%9}, {%0,%1,%2,%3};"
        : "+f"(c[0]), "+f"(c[1]), "+f"(c[2]), "+f"(c[3])
        : "r"(a0), "r"(a1), "r"(a2), "r"(a3), "r"(b0), "r"(b1));
}

// ---------------------------------------------------------------- main kernel
// One CTA = one kernel offset k; persistent over P-tiles t = bx, bx+GX, ...
// 256 threads, 8 warps in 2(row-half) x 4(col-quarter) grid: warp owns 64 rows
// x 32 cols. B fragments (128 regs) resident all kernel. A double-buffered in
// smem, XOR-swizzled (conflict-free LDS.128 reads AND STS.128 writes), with
// register-prefetched gather overlapping the MMA phase.
//
// A layout: row r (stride 128 floats), 16-col group kp stores its 4x4-transposed
// uint4 slot i at chunk (kp ^ (r&7))*4 + i.  Reader (lane g,tig) loads chunk
// (kp^g)*4 + tig -> {cols tig,tig+4,tig+8,tig+12} = A-frags for k-steps 2kp,2kp+1.
__global__ void __launch_bounds__(THREADS, 1)
spconv_mma_kernel(const float* __restrict__ X,
                  const float* __restrict__ Wt,     // [KOFF][n][c], tf32-rounded
                  const int* __restrict__ in_map,
                  const int* __restrict__ out_map,
                  float* __restrict__ Y,
                  int do_relu)
{
    extern __shared__ float As[];                  // [2][TILE_M][128]
    const int tid = threadIdx.x;
    const int wid = tid >> 5, lid = tid & 31;
    const int g = lid >> 2, tig = lid & 3;         // groupID / thread-in-group
    const int rb = wid >> 2;                       // row half (0/1)
    const int n0 = (wid & 3) * 32;                 // col quarter base
    const int k = blockIdx.y;
    const int* im = in_map  + k * NPAIRS;
    const int* om = out_map + k * NPAIRS;

    // gather role: 2 threads per row
    const int gr = tid >> 1, gh = tid & 1;         // row 0..127, half 0/1

    // ---- load B fragments once: bfr[ks][nb][i] = Wt[k][n0+8nb+g][8ks+tig+4i] ----
    uint32_t bfr[16][4][2];
    {
        const float* wk = Wt + (size_t)k * C * C;
        #pragma unroll
        for (int ks = 0; ks < 16; ks++)
            #pragma unroll
            for (int nb = 0; nb < 4; nb++) {
                const float* wrow = wk + (n0 + 8 * nb + g) * C + 8 * ks + tig;
                bfr[ks][nb][0] = __float_as_uint(wrow[0]);
                bfr[ks][nb][1] = __float_as_uint(wrow[4]);
            }
    }

    float4 gbuf[16];                               // prefetched half-row (64 regs)

    // prologue prefetch: tile t0
    {
        int p  = blockIdx.x * TILE_M + gr;
        int pv = p < NPAIRS ? p : NPAIRS - 1;
        const float4* xr = reinterpret_cast<const float4*>(X + (size_t)im[pv] * C);
        #pragma unroll
        for (int q = 0; q < 16; q++) gbuf[q] = xr[gh * 16 + q];
    }

    int cur = 0;
    for (int t = blockIdx.x; t < NTILES; t += GX) {
        // ---- store prefetched data: relu + cvt + 4x4 transpose + XOR swizzle ----
        {
            float* dst = As + cur * BUFW + gr * C;
            const int key = (gr & 7);
            #pragma unroll
            for (int jj = 0; jj < 4; jj++) {
                int kp = gh * 4 + jj;
                float4 x0 = gbuf[jj*4+0], x1 = gbuf[jj*4+1];
                float4 x2 = gbuf[jj*4+2], x3 = gbuf[jj*4+3];
                if (do_relu) {
                    x0.x=fmaxf(x0.x,0.f); x0.y=fmaxf(x0.y,0.f); x0.z=fmaxf(x0.z,0.f); x0.w=fmaxf(x0.w,0.f);
                    x1.x=fmaxf(x1.x,0.f); x1.y=fmaxf(x1.y,0.f); x1.z=fmaxf(x1.z,0.f); x1.w=fmaxf(x1.w,0.f);
                    x2.x=fmaxf(x2.x,0.f); x2.y=fmaxf(x2.y,0.f); x2.z=fmaxf(x2.z,0.f); x2.w=fmaxf(x2.w,0.f);
                    x3.x=fmaxf(x3.x,0.f); x3.y=fmaxf(x3.y,0.f); x3.z=fmaxf(x3.z,0.f); x3.w=fmaxf(x3.w,0.f);
                }
                uint4 o0 = { cvt_tf32(x0.x), cvt_tf32(x1.x), cvt_tf32(x2.x), cvt_tf32(x3.x) };
                uint4 o1 = { cvt_tf32(x0.y), cvt_tf32(x1.y), cvt_tf32(x2.y), cvt_tf32(x3.y) };
                uint4 o2 = { cvt_tf32(x0.z), cvt_tf32(x1.z), cvt_tf32(x2.z), cvt_tf32(x3.z) };
                uint4 o3 = { cvt_tf32(x0.w), cvt_tf32(x1.w), cvt_tf32(x2.w), cvt_tf32(x3.w) };
                float* cbase = dst + ((kp ^ key) << 4);  // chunk quad base (16 words)
                *reinterpret_cast<uint4*>(cbase +  0) = o0;
                *reinterpret_cast<uint4*>(cbase +  4) = o1;
                *reinterpret_cast<uint4*>(cbase +  8) = o2;
                *reinterpret_cast<uint4*>(cbase + 12) = o3;
            }
        }
        __syncthreads();

        // ---- prefetch next tile (LDGs land during MMA phase) ----
        int tn = t + GX;
        if (tn < NTILES) {
            int p  = tn * TILE_M + gr;
            int pv = p < NPAIRS ? p : NPAIRS - 1;
            const float4* xr = reinterpret_cast<const float4*>(X + (size_t)im[pv] * C);
            #pragma unroll
            for (int q = 0; q < 16; q++) gbuf[q] = xr[gh * 16 + q];
        }

        // ---- MMA + scatter on buf[cur] ----
        const float* abuf = As + cur * BUFW;
        #pragma unroll 1
        for (int mb = 0; mb < 4; mb++) {
            float acc[4][4] = {{0.f,0.f,0.f,0.f},{0.f,0.f,0.f,0.f},
                               {0.f,0.f,0.f,0.f},{0.f,0.f,0.f,0.f}};
            const int row_lo = rb * 64 + mb * 16 + g;
            const float* a_lo = abuf + row_lo * C;
            const float* a_hi = a_lo + 8 * C;
            #pragma unroll
            for (int kp = 0; kp < 8; kp++) {
                const int co = (((kp ^ g) << 2) + tig) << 2;   // word offset of chunk
                uint4 lo = *reinterpret_cast<const uint4*>(a_lo + co);
                uint4 hi = *reinterpret_cast<const uint4*>(a_hi + co);
                #pragma unroll
                for (int nb = 0; nb < 4; nb++) {
                    mma_tf32(acc[nb], lo.x, hi.x, lo.y, hi.y,
                             bfr[2*kp  ][nb][0], bfr[2*kp  ][nb][1]);
                    mma_tf32(acc[nb], lo.z, hi.z, lo.w, hi.w,
                             bfr[2*kp+1][nb][0], bfr[2*kp+1][nb][1]);
                }
            }
            int p_lo = t * TILE_M + row_lo;
            int p_hi = p_lo + 8;
            if (p_lo < NPAIRS) {
                float* y = Y + (size_t)om[p_lo] * C + n0 + 2 * tig;
                #pragma unroll
                for (int nb = 0; nb < 4; nb++)
                    red_add_v2(y + 8 * nb, acc[nb][0], acc[nb][1]);
            }
            if (p_hi < NPAIRS) {
                float* y = Y + (size_t)om[p_hi] * C + n0 + 2 * tig;
                #pragma unroll
                for (int nb = 0; nb < 4; nb++)
                    red_add_v2(y + 8 * nb, acc[nb][2], acc[nb][3]);
            }
        }
        cur ^= 1;
    }
}

// ---------------------------------------------------------------- small kernels
__global__ void wt_kernel(const float* __restrict__ W0, const float* __restrict__ W1) {
    int i = blockIdx.x * blockDim.x + threadIdx.x;       // over KOFF*C*C, layout [k][n][c]
    if (i >= KOFF * C * C) return;
    int k = i / (C * C);
    int rem = i % (C * C);
    int n = rem / C, c = rem % C;
    g_Wt[i] = __uint_as_float(cvt_tf32(W0[(size_t)k * C * C + c * C + n]));
    g_Wt[(size_t)KOFF * C * C + i] =
        __uint_as_float(cvt_tf32(W1[(size_t)k * C * C + c * C + n]));
}

__global__ void init_h_kernel(const float* __restrict__ b0) {
    int i = blockIdx.x * blockDim.x + threadIdx.x;       // float4 index
    if (i < NPTS * C / 4)
        reinterpret_cast<float4*>(g_h)[i] =
            reinterpret_cast<const float4*>(b0)[i & (C / 4 - 1)];
}

__global__ void init_out_kernel(const float* __restrict__ feat,
                                const float* __restrict__ b1,
                                float* __restrict__ out) {
    int i = blockIdx.x * blockDim.x + threadIdx.x;
    if (i < NPTS * C / 4) {
        float4 f = reinterpret_cast<const float4*>(feat)[i];
        float4 b = reinterpret_cast<const float4*>(b1)[i & (C / 4 - 1)];
        f.x += b.x; f.y += b.y; f.z += b.z; f.w += b.w;
        reinterpret_cast<float4*>(out)[i] = f;
    }
}

// ---------------------------------------------------------------- launch
extern "C" void kernel_launch(void* const* d_in, const int* in_sizes, int n_in,
                              void* d_out, int out_size) {
    const float* feat    = (const float*)d_in[0];
    const int*   in_map  = (const int*)  d_in[1];
    const int*   out_map = (const int*)  d_in[2];
    const float* W0      = (const float*)d_in[3];
    const float* b0      = (const float*)d_in[4];
    const float* W1      = (const float*)d_in[5];
    const float* b1      = (const float*)d_in[6];
    float*       out     = (float*)d_out;

    float* h  = nullptr; cudaGetSymbolAddress((void**)&h,  g_h);
    float* wt = nullptr; cudaGetSymbolAddress((void**)&wt, g_Wt);

    const int smem_bytes = 2 * BUFW * (int)sizeof(float);   // 131072
    cudaFuncSetAttribute(spconv_mma_kernel,
                         cudaFuncAttributeMaxDynamicSharedMemorySize, smem_bytes);

    const int nv4 = NPTS * C / 4;
    dim3 ggrid(GX, KOFF);

    wt_kernel<<<(KOFF * C * C + 255) / 256, 256>>>(W0, W1);

    // conv0: h = b0; h += scatter(gather(x) @ W0)   (relu deferred into conv1's gather)
    init_h_kernel<<<(nv4 + 255) / 256, 256>>>(b0);
    spconv_mma_kernel<<<ggrid, THREADS, smem_bytes>>>(feat, wt, in_map, out_map, h, 0);

    // conv1: out = x + b1; out += scatter(gather(relu(h)) @ W1)
    init_out_kernel<<<(nv4 + 255) / 256, 256>>>(feat, b1, out);
    spconv_mma_kernel<<<ggrid, THREADS, smem_bytes>>>(h, wt + (size_t)KOFF * C * C,
                                                     in_map, out_map, out, 1);
}

// round 13
// speedup vs baseline: 1.9068x; 1.3417x over previous
#include <cuda_runtime.h>
#include <cstdint>

#define DINLINE __device__ __forceinline__

constexpr int NPTS   = 100000;
constexpr int NPAIRS = 50000;
constexpr int KOFF   = 27;
constexpr int C      = 128;
constexpr int TILE_M = 128;
constexpr int NTILES = (NPAIRS + TILE_M - 1) / TILE_M;    // 391
constexpr int JT     = KOFF * NTILES;                     // 10557 jobs
constexpr int NCTA   = 148;                               // 1 CTA/SM, full chip
constexpr int JBASE  = JT / NCTA;                         // 71
constexpr int JREM   = JT % NCTA;                         // 49
constexpr int THREADS = 256;
constexpr int BUFW   = TILE_M * C;                        // 16384 words / buffer

// scratch: intermediate activations + pre-transposed tf32 weights
__device__ float g_h[(size_t)NPTS * C];
__device__ float g_Wt[(size_t)2 * KOFF * C * C];          // [conv][k][n][c], tf32-rounded

// ---------------------------------------------------------------- helpers
DINLINE uint32_t cvt_tf32(float f) {
    uint32_t r; asm("cvt.rna.tf32.f32 %0, %1;" : "=r"(r) : "f"(f)); return r;
}
DINLINE void red_add_v4(float* a, float x, float y, float z, float w) {
    asm volatile("red.global.add.v4.f32 [%0], {%1,%2,%3,%4};"
                 :: "l"(a), "f"(x), "f"(y), "f"(z), "f"(w) : "memory");
}
// m16n8k8 tf32 mma: A row-major frag {a0..a3}, B col-major frag {b0,b1}, fp32 acc
DINLINE void mma_tf32(float c[4], uint32_t a0, uint32_t a1, uint32_t a2, uint32_t a3,
                      uint32_t b0, uint32_t b1) {
    asm volatile(
        "mma.sync.aligned.m16n8k8.row.col.f32.tf32.tf32.f32 "
        "{%0,%1,%2,%3}, {%4,%5,%6,%7}, {%8,%9}, {%0,%1,%2,%3};"
        : "+f"(c[0]), "+f"(c[1]), "+f"(c[2]), "+f"(c[3])
        : "r"(a0), "r"(a1), "r"(a2), "r"(a3), "r"(b0), "r"(b1));
}

// ---------------------------------------------------------------- main kernel
// 148 persistent CTAs over (k, tile) jobs, contiguous blocks (<=1 W reload/CTA).
// 256 threads, 8 warps in 2(row-half) x 4(col-quarter): warp owns 64 rows x 32
// cols. B fragments (128 regs) resident. A double-buffered in smem with natural
// row layout + per-row XOR-4 float4 swizzle:
//   word (row, w) stored at row*128 + (((w>>2) ^ (row&7))<<2) + (w&3)
// Gather: 8 threads/row, lanes read consecutive float4s (4 lines / LDG instr).
// MMA reads: 4x LDS.32 per k-step, conflict-free by the swizzle.
// Scatter: accumulator quad-shuffle -> red.global.add.v4 (half the lane-ops).
__global__ void __launch_bounds__(THREADS, 1)
spconv_mma_kernel(const float* __restrict__ X,
                  const float* __restrict__ Wt,     // [KOFF][n][c], tf32-rounded
                  const int* __restrict__ in_map,
                  const int* __restrict__ out_map,
                  float* __restrict__ Y,
                  int do_relu)
{
    extern __shared__ float As[];                  // [2][TILE_M][128]
    const int tid = threadIdx.x;
    const int wid = tid >> 5, lid = tid & 31;
    const int g = lid >> 2, tig = lid & 3;         // groupID / thread-in-group
    const int rb = wid >> 2;                       // row half (0/1)
    const int n0 = (wid & 3) * 32;                 // col quarter base
    const int gr8 = tid >> 3, ge = tid & 7;        // gather: row-in-pass / float4 lane

    const int cta  = blockIdx.x;
    const int jbeg = cta * JBASE + (cta < JREM ? cta : JREM);
    const int jend = jbeg + JBASE + (cta < JREM ? 1 : 0);

    uint32_t bfr[16][4][2];
    int kcur = -1;

    float4 gbuf[16];                               // prefetched gather data (64 regs)

    // prologue prefetch: job jbeg
    {
        int k0 = jbeg / NTILES, t0 = jbeg % NTILES;
        const int* im = in_map + k0 * NPAIRS;
        #pragma unroll
        for (int pp = 0; pp < 4; pp++) {
            int p  = t0 * TILE_M + pp * 32 + gr8;
            int pv = p < NPAIRS ? p : NPAIRS - 1;
            const float4* xr = reinterpret_cast<const float4*>(X + (size_t)im[pv] * C);
            #pragma unroll
            for (int jj = 0; jj < 4; jj++) gbuf[pp * 4 + jj] = xr[ge + 8 * jj];
        }
    }

    int cur = 0;
    for (int jid = jbeg; jid < jend; jid++) {
        const int k = jid / NTILES, t = jid % NTILES;

        // ---- (re)load B fragments on k change: bfr[ks][nb][i] = Wt[k][n][8ks+tig+4i]
        if (k != kcur) {
            kcur = k;
            const float* wk = Wt + (size_t)k * C * C;
            #pragma unroll
            for (int ks = 0; ks < 16; ks++)
                #pragma unroll
                for (int nb = 0; nb < 4; nb++) {
                    const float* wrow = wk + (n0 + 8 * nb + g) * C + 8 * ks + tig;
                    bfr[ks][nb][0] = __float_as_uint(wrow[0]);
                    bfr[ks][nb][1] = __float_as_uint(wrow[4]);
                }
        }

        // ---- store prefetched tile: relu + cvt + XOR swizzle ----
        {
            float* dst0 = As + cur * BUFW;
            #pragma unroll
            for (int pp = 0; pp < 4; pp++) {
                int r = pp * 32 + gr8;
                int key = r & 7;
                float* rowp = dst0 + r * C;
                #pragma unroll
                for (int jj = 0; jj < 4; jj++) {
                    float4 v = gbuf[pp * 4 + jj];
                    if (do_relu) {
                        v.x = fmaxf(v.x, 0.f); v.y = fmaxf(v.y, 0.f);
                        v.z = fmaxf(v.z, 0.f); v.w = fmaxf(v.w, 0.f);
                    }
                    uint4 o = { cvt_tf32(v.x), cvt_tf32(v.y), cvt_tf32(v.z), cvt_tf32(v.w) };
                    int f = ge + 8 * jj;
                    *reinterpret_cast<uint4*>(rowp + (((f ^ key)) << 2)) = o;
                }
            }
        }
        __syncthreads();

        // ---- prefetch next job (LDGs land during MMA phase) ----
        if (jid + 1 < jend) {
            int k2 = (jid + 1) / NTILES, t2 = (jid + 1) % NTILES;
            const int* im = in_map + k2 * NPAIRS;
            #pragma unroll
            for (int pp = 0; pp < 4; pp++) {
                int p  = t2 * TILE_M + pp * 32 + gr8;
                int pv = p < NPAIRS ? p : NPAIRS - 1;
                const float4* xr = reinterpret_cast<const float4*>(X + (size_t)im[pv] * C);
                #pragma unroll
                for (int jj = 0; jj < 4; jj++) gbuf[pp * 4 + jj] = xr[ge + 8 * jj];
            }
        }

        // ---- MMA + scatter on buf[cur] ----
        const float* abuf = As + cur * BUFW;
        const int* om = out_map + k * NPAIRS;
        #pragma unroll 1
        for (int mb = 0; mb < 4; mb++) {
            float acc[4][4] = {{0.f,0.f,0.f,0.f},{0.f,0.f,0.f,0.f},
                               {0.f,0.f,0.f,0.f},{0.f,0.f,0.f,0.f}};
            const int row_lo = rb * 64 + mb * 16 + g;
            const float* a_lo = abuf + row_lo * C;
            const float* a_hi = a_lo + 8 * C;
            #pragma unroll
            for (int ks = 0; ks < 16; ks++) {
                const int f0 = ((2 * ks    ) ^ g) << 2;    // swizzled float4 base
                const int f1 = ((2 * ks + 1) ^ g) << 2;
                uint32_t a0 = __float_as_uint(a_lo[f0 + tig]);
                uint32_t a1 = __float_as_uint(a_hi[f0 + tig]);
                uint32_t a2 = __float_as_uint(a_lo[f1 + tig]);
                uint32_t a3 = __float_as_uint(a_hi[f1 + tig]);
                #pragma unroll
                for (int nb = 0; nb < 4; nb++)
                    mma_tf32(acc[nb], a0, a1, a2, a3, bfr[ks][nb][0], bfr[ks][nb][1]);
            }

            // epilogue: quad butterfly -> red.v4 (16B per lane)
            int p_lo = t * TILE_M + row_lo;
            int p_hi = p_lo + 8;
            int d_lo = (p_lo < NPAIRS) ? om[p_lo] : -1;
            int d_hi = (p_hi < NPAIRS) ? om[p_hi] : -1;
            int dst  = (tig & 1) ? d_hi : d_lo;
            float* ybase = (dst >= 0)
                ? Y + (size_t)dst * C + n0 + ((tig >> 1) << 2) : nullptr;
            #pragma unroll
            for (int nb = 0; nb < 4; nb++) {
                // even lanes need partner's (c0,c1); odd lanes partner's (c2,c3)
                float s0 = (tig & 1) ? acc[nb][0] : acc[nb][2];
                float s1 = (tig & 1) ? acc[nb][1] : acc[nb][3];
                float r0 = __shfl_xor_sync(0xffffffffu, s0, 1);
                float r1 = __shfl_xor_sync(0xffffffffu, s1, 1);
                float q0 = (tig & 1) ? r0 : acc[nb][0];
                float q1 = (tig & 1) ? r1 : acc[nb][1];
                float q2 = (tig & 1) ? acc[nb][2] : r0;
                float q3 = (tig & 1) ? acc[nb][3] : r1;
                if (ybase) red_add_v4(ybase + 8 * nb, q0, q1, q2, q3);
            }
        }
        cur ^= 1;
    }
}

// ---------------------------------------------------------------- small kernels
__global__ void wt_kernel(const float* __restrict__ W0, const float* __restrict__ W1) {
    int i = blockIdx.x * blockDim.x + threadIdx.x;       // over KOFF*C*C, layout [k][n][c]
    if (i >= KOFF * C * C) return;
    int k = i / (C * C);
    int rem = i % (C * C);
    int n = rem / C, c = rem % C;
    g_Wt[i] = __uint_as_float(cvt_tf32(W0[(size_t)k * C * C + c * C + n]));
    g_Wt[(size_t)KOFF * C * C + i] =
        __uint_as_float(cvt_tf32(W1[(size_t)k * C * C + c * C + n]));
}

__global__ void init_h_kernel(const float* __restrict__ b0) {
    int i = blockIdx.x * blockDim.x + threadIdx.x;       // float4 index
    if (i < NPTS * C / 4)
        reinterpret_cast<float4*>(g_h)[i] =
            reinterpret_cast<const float4*>(b0)[i & (C / 4 - 1)];
}

__global__ void init_out_kernel(const float* __restrict__ feat,
                                const float* __restrict__ b1,
                                float* __restrict__ out) {
    int i = blockIdx.x * blockDim.x + threadIdx.x;
    if (i < NPTS * C / 4) {
        float4 f = reinterpret_cast<const float4*>(feat)[i];
        float4 b = reinterpret_cast<const float4*>(b1)[i & (C / 4 - 1)];
        f.x += b.x; f.y += b.y; f.z += b.z; f.w += b.w;
        reinterpret_cast<float4*>(out)[i] = f;
    }
}

// ---------------------------------------------------------------- launch
extern "C" void kernel_launch(void* const* d_in, const int* in_sizes, int n_in,
                              void* d_out, int out_size) {
    const float* feat    = (const float*)d_in[0];
    const int*   in_map  = (const int*)  d_in[1];
    const int*   out_map = (const int*)  d_in[2];
    const float* W0      = (const float*)d_in[3];
    const float* b0      = (const float*)d_in[4];
    const float* W1      = (const float*)d_in[5];
    const float* b1      = (const float*)d_in[6];
    float*       out     = (float*)d_out;

    float* h  = nullptr; cudaGetSymbolAddress((void**)&h,  g_h);
    float* wt = nullptr; cudaGetSymbolAddress((void**)&wt, g_Wt);

    const int smem_bytes = 2 * BUFW * (int)sizeof(float);   // 131072
    cudaFuncSetAttribute(spconv_mma_kernel,
                         cudaFuncAttributeMaxDynamicSharedMemorySize, smem_bytes);

    const int nv4 = NPTS * C / 4;

    wt_kernel<<<(KOFF * C * C + 255) / 256, 256>>>(W0, W1);

    // conv0: h = b0; h += scatter(gather(x) @ W0)   (relu deferred into conv1's gather)
    init_h_kernel<<<(nv4 + 255) / 256, 256>>>(b0);
    spconv_mma_kernel<<<NCTA, THREADS, smem_bytes>>>(feat, wt, in_map, out_map, h, 0);

    // conv1: out = x + b1; out += scatter(gather(relu(h)) @ W1)
    init_out_kernel<<<(nv4 + 255) / 256, 256>>>(feat, b1, out);
    spconv_mma_kernel<<<NCTA, THREADS, smem_bytes>>>(h, wt + (size_t)KOFF * C * C,
                                                    in_map, out_map, out, 1);
}

// round 14
// speedup vs baseline: 2.4677x; 1.2942x over previous
#include <cuda_runtime.h>
#include <cuda_fp16.h>
#include <cstdint>

#define DINLINE __device__ __forceinline__

constexpr int NPTS   = 100000;
constexpr int NPAIRS = 50000;
constexpr int KOFF   = 27;
constexpr int C      = 128;
constexpr int TILE_M = 128;
constexpr int NTILES = (NPAIRS + TILE_M - 1) / TILE_M;    // 391
constexpr int JT     = KOFF * NTILES;                     // 10557 jobs
constexpr int NCTA   = 148;                               // 1 CTA/SM, full chip
constexpr int JBASE  = JT / NCTA;                         // 71
constexpr int JREM   = JT % NCTA;                         // 49
constexpr int THREADS = 256;
constexpr int ROWW   = 68;                                // uint32 words/row (64 data + 4 pad)
constexpr int BUFW32 = TILE_M * ROWW;                     // 8704 words / buffer

// scratch: intermediate activations + pre-transposed fp16 weights
__device__ float  g_h[(size_t)NPTS * C];
__device__ __half g_Wh[(size_t)2 * KOFF * C * C];         // [conv][k][n][c], fp16

// ---------------------------------------------------------------- helpers
DINLINE void red_add_v4(float* a, float x, float y, float z, float w) {
    asm volatile("red.global.add.v4.f32 [%0], {%1,%2,%3,%4};"
                 :: "l"(a), "f"(x), "f"(y), "f"(z), "f"(w) : "memory");
}
// m16n8k16 fp16 mma: A row-major frag {a0..a3}, B col-major frag {b0,b1}, fp32 acc
DINLINE void mma_f16(float c[4], uint32_t a0, uint32_t a1, uint32_t a2, uint32_t a3,
                     uint32_t b0, uint32_t b1) {
    asm volatile(
        "mma.sync.aligned.m16n8k16.row.col.f32.f16.f16.f32 "
        "{%0,%1,%2,%3}, {%4,%5,%6,%7}, {%8,%9}, {%0,%1,%2,%3};"
        : "+f"(c[0]), "+f"(c[1]), "+f"(c[2]), "+f"(c[3])
        : "r"(a0), "r"(a1), "r"(a2), "r"(a3), "r"(b0), "r"(b1));
}

// ---------------------------------------------------------------- main kernel
// 148 persistent CTAs over (k, tile) jobs, contiguous blocks (<=1 W reload/CTA).
// 256 threads, 8 warps in 2(row-half) x 4(col-quarter): warp owns 64 rows x 32
// cols. fp16 B fragments (64 regs) resident. A tile fp16 in smem, rows padded
// to 68 words: bank = (4*row + word) mod 32, so the 32 MMA-read lanes
// (8 g x 4 tig -> 4g + tig) hit 32 distinct banks. Double buffered, register-
// prefetched gather (8 threads/row, consecutive float4s = 4 lines/LDG).
// Scatter: quad butterfly -> red.global.add.v4.
__global__ void __launch_bounds__(THREADS, 1)
spconv_mma_kernel(const float* __restrict__ X,
                  const __half* __restrict__ Wh,    // [KOFF][n][c], fp16
                  const int* __restrict__ in_map,
                  const int* __restrict__ out_map,
                  float* __restrict__ Y,
                  int do_relu)
{
    extern __shared__ __align__(16) uint32_t As[]; // [2][BUFW32]
    const int tid = threadIdx.x;
    const int wid = tid >> 5, lid = tid & 31;
    const int g = lid >> 2, tig = lid & 3;         // groupID / thread-in-group
    const int rb = wid >> 2;                       // row half (0/1)
    const int n0 = (wid & 3) * 32;                 // col quarter base
    const int gr8 = tid >> 3, ge = tid & 7;        // gather: row-in-pass / float4 lane

    const int cta  = blockIdx.x;
    const int jbeg = cta * JBASE + (cta < JREM ? cta : JREM);
    const int jend = jbeg + JBASE + (cta < JREM ? 1 : 0);

    uint32_t bfr[8][4][2];                         // fp16 B fragments (64 regs)
    int kcur = -1;

    float4 gbuf[16];                               // prefetched gather data (64 regs)

    // prologue prefetch: job jbeg
    {
        int k0 = jbeg / NTILES, t0 = jbeg % NTILES;
        const int* im = in_map + k0 * NPAIRS;
        #pragma unroll
        for (int pp = 0; pp < 4; pp++) {
            int p  = t0 * TILE_M + pp * 32 + gr8;
            int pv = p < NPAIRS ? p : NPAIRS - 1;
            const float4* xr = reinterpret_cast<const float4*>(X + (size_t)im[pv] * C);
            #pragma unroll
            for (int jj = 0; jj < 4; jj++) gbuf[pp * 4 + jj] = xr[ge + 8 * jj];
        }
    }

    int cur = 0;
    for (int jid = jbeg; jid < jend; jid++) {
        const int k = jid / NTILES, t = jid % NTILES;

        // ---- (re)load B fragments on k change ----
        // bfr[ks][nb][0] = halves W[n0+8nb+g][16ks+2tig, +1]; [1] = cols +8,+9
        if (k != kcur) {
            kcur = k;
            const __half* wk = Wh + (size_t)k * C * C;
            #pragma unroll
            for (int ks = 0; ks < 8; ks++)
                #pragma unroll
                for (int nb = 0; nb < 4; nb++) {
                    const __half* wrow = wk + (n0 + 8 * nb + g) * C + 16 * ks + 2 * tig;
                    bfr[ks][nb][0] = *reinterpret_cast<const uint32_t*>(wrow);
                    bfr[ks][nb][1] = *reinterpret_cast<const uint32_t*>(wrow + 8);
                }
        }

        // ---- store prefetched tile: relu + cvt fp16 ----
        {
            uint32_t* dst0 = As + cur * BUFW32;
            #pragma unroll
            for (int pp = 0; pp < 4; pp++) {
                int r = pp * 32 + gr8;
                uint32_t* rowp = dst0 + r * ROWW;
                #pragma unroll
                for (int jj = 0; jj < 4; jj++) {
                    float4 v = gbuf[pp * 4 + jj];
                    if (do_relu) {
                        v.x = fmaxf(v.x, 0.f); v.y = fmaxf(v.y, 0.f);
                        v.z = fmaxf(v.z, 0.f); v.w = fmaxf(v.w, 0.f);
                    }
                    __half2 h01 = __floats2half2_rn(v.x, v.y);
                    __half2 h23 = __floats2half2_rn(v.z, v.w);
                    uint2 o;
                    o.x = *reinterpret_cast<uint32_t*>(&h01);
                    o.y = *reinterpret_cast<uint32_t*>(&h23);
                    *reinterpret_cast<uint2*>(rowp + 2 * (ge + 8 * jj)) = o;
                }
            }
        }
        __syncthreads();

        // ---- prefetch next job (LDGs land during MMA phase) ----
        if (jid + 1 < jend) {
            int k2 = (jid + 1) / NTILES, t2 = (jid + 1) % NTILES;
            const int* im = in_map + k2 * NPAIRS;
            #pragma unroll
            for (int pp = 0; pp < 4; pp++) {
                int p  = t2 * TILE_M + pp * 32 + gr8;
                int pv = p < NPAIRS ? p : NPAIRS - 1;
                const float4* xr = reinterpret_cast<const float4*>(X + (size_t)im[pv] * C);
                #pragma unroll
                for (int jj = 0; jj < 4; jj++) gbuf[pp * 4 + jj] = xr[ge + 8 * jj];
            }
        }

        // ---- MMA + scatter on buf[cur] ----
        const uint32_t* abuf = As + cur * BUFW32;
        const int* om = out_map + k * NPAIRS;
        #pragma unroll 1
        for (int mb = 0; mb < 4; mb++) {
            float acc[4][4] = {{0.f,0.f,0.f,0.f},{0.f,0.f,0.f,0.f},
                               {0.f,0.f,0.f,0.f},{0.f,0.f,0.f,0.f}};
            const int row_lo = rb * 64 + mb * 16 + g;
            const uint32_t* a_lo = abuf + row_lo * ROWW;
            const uint32_t* a_hi = a_lo + 8 * ROWW;
            #pragma unroll
            for (int ks = 0; ks < 8; ks++) {
                uint32_t a0 = a_lo[ks * 8 + tig];
                uint32_t a1 = a_hi[ks * 8 + tig];
                uint32_t a2 = a_lo[ks * 8 + tig + 4];
                uint32_t a3 = a_hi[ks * 8 + tig + 4];
                #pragma unroll
                for (int nb = 0; nb < 4; nb++)
                    mma_f16(acc[nb], a0, a1, a2, a3, bfr[ks][nb][0], bfr[ks][nb][1]);
            }

            // epilogue: quad butterfly -> red.v4 (16B per lane)
            int p_lo = t * TILE_M + row_lo;
            int p_hi = p_lo + 8;
            int d_lo = (p_lo < NPAIRS) ? om[p_lo] : -1;
            int d_hi = (p_hi < NPAIRS) ? om[p_hi] : -1;
            int dst  = (tig & 1) ? d_hi : d_lo;
            float* ybase = (dst >= 0)
                ? Y + (size_t)dst * C + n0 + ((tig >> 1) << 2) : nullptr;
            #pragma unroll
            for (int nb = 0; nb < 4; nb++) {
                // even lanes need partner's (c0,c1); odd lanes partner's (c2,c3)
                float s0 = (tig & 1) ? acc[nb][0] : acc[nb][2];
                float s1 = (tig & 1) ? acc[nb][1] : acc[nb][3];
                float r0 = __shfl_xor_sync(0xffffffffu, s0, 1);
                float r1 = __shfl_xor_sync(0xffffffffu, s1, 1);
                float q0 = (tig & 1) ? r0 : acc[nb][0];
                float q1 = (tig & 1) ? r1 : acc[nb][1];
                float q2 = (tig & 1) ? acc[nb][2] : r0;
                float q3 = (tig & 1) ? acc[nb][3] : r1;
                if (ybase) red_add_v4(ybase + 8 * nb, q0, q1, q2, q3);
            }
        }
        cur ^= 1;
    }
}

// ---------------------------------------------------------------- small kernels
__global__ void wt_kernel(const float* __restrict__ W0, const float* __restrict__ W1) {
    int i = blockIdx.x * blockDim.x + threadIdx.x;       // over KOFF*C*C, layout [k][n][c]
    if (i >= KOFF * C * C) return;
    int k = i / (C * C);
    int rem = i % (C * C);
    int n = rem / C, c = rem % C;
    g_Wh[i] = __float2half_rn(W0[(size_t)k * C * C + c * C + n]);
    g_Wh[(size_t)KOFF * C * C + i] = __float2half_rn(W1[(size_t)k * C * C + c * C + n]);
}

__global__ void init_h_kernel(const float* __restrict__ b0) {
    int i = blockIdx.x * blockDim.x + threadIdx.x;       // float4 index
    if (i < NPTS * C / 4)
        reinterpret_cast<float4*>(g_h)[i] =
            reinterpret_cast<const float4*>(b0)[i & (C / 4 - 1)];
}

__global__ void init_out_kernel(const float* __restrict__ feat,
                                const float* __restrict__ b1,
                                float* __restrict__ out) {
    int i = blockIdx.x * blockDim.x + threadIdx.x;
    if (i < NPTS * C / 4) {
        float4 f = reinterpret_cast<const float4*>(feat)[i];
        float4 b = reinterpret_cast<const float4*>(b1)[i & (C / 4 - 1)];
        f.x += b.x; f.y += b.y; f.z += b.z; f.w += b.w;
        reinterpret_cast<float4*>(out)[i] = f;
    }
}

// ---------------------------------------------------------------- launch
extern "C" void kernel_launch(void* const* d_in, const int* in_sizes, int n_in,
                              void* d_out, int out_size) {
    const float* feat    = (const float*)d_in[0];
    const int*   in_map  = (const int*)  d_in[1];
    const int*   out_map = (const int*)  d_in[2];
    const float* W0      = (const float*)d_in[3];
    const float* b0      = (const float*)d_in[4];
    const float* W1      = (const float*)d_in[5];
    const float* b1      = (const float*)d_in[6];
    float*       out     = (float*)d_out;

    float*  h  = nullptr; cudaGetSymbolAddress((void**)&h,  g_h);
    __half* wh = nullptr; cudaGetSymbolAddress((void**)&wh, g_Wh);

    const int smem_bytes = 2 * BUFW32 * (int)sizeof(uint32_t);   // 69632
    cudaFuncSetAttribute(spconv_mma_kernel,
                         cudaFuncAttributeMaxDynamicSharedMemorySize, smem_bytes);

    const int nv4 = NPTS * C / 4;

    wt_kernel<<<(KOFF * C * C + 255) / 256, 256>>>(W0, W1);

    // conv0: h = b0; h += scatter(gather(x) @ W0)   (relu deferred into conv1's gather)
    init_h_kernel<<<(nv4 + 255) / 256, 256>>>(b0);
    spconv_mma_kernel<<<NCTA, THREADS, smem_bytes>>>(feat, wh, in_map, out_map, h, 0);

    // conv1: out = x + b1; out += scatter(gather(relu(h)) @ W1)
    init_out_kernel<<<(nv4 + 255) / 256, 256>>>(feat, b1, out);
    spconv_mma_kernel<<<NCTA, THREADS, smem_bytes>>>(h, wh + (size_t)KOFF * C * C,
                                                    in_map, out_map, out, 1);
}